// round 12
// baseline (speedup 1.0000x reference)
#include <cuda_runtime.h>
#include <math.h>

__constant__ float c_primes[24] = {2, 3, 5, 7, 11, 13, 17, 19, 23, 29, 31, 37,
                                   41, 43, 47, 53, 59, 61, 67, 71, 73, 79, 83, 89};

// FFT4 -> pointwise filter -> IFFT4 -> Re() collapses to a real 4x4 circulant.
// Each warp is fully self-contained: issue GPT coalesced .cs loads FIRST, then
// compute the 4 circulant coefficients redundantly per-warp (lanes 0-23 one
// prime each, shfl_xor butterfly reduce -> sums in every lane, tiny local
// IFFT). No smem, no __syncthreads: prologue hides under DRAM load latency.
#define GPT 4
#define NTHR 256

__global__ void __launch_bounds__(NTHR)
fused_resonant_kernel(const float4* __restrict__ x,
                      float4* __restrict__ y,
                      const float* __restrict__ amp,
                      const float* __restrict__ phase,
                      int n_groups) {
    int base = blockIdx.x * (NTHR * GPT) + threadIdx.x;
    bool fast = (base + (GPT - 1) * NTHR < n_groups);

    // 1) Issue streaming loads first (independent of coefficients).
    float4 v[GPT];
    if (fast) {
        #pragma unroll
        for (int g = 0; g < GPT; g++)
            v[g] = __ldcs(&x[base + g * NTHR]);
    }

    // 2) Per-warp coefficient computation, overlapped with in-flight loads.
    const float PI = 3.14159265358979323846f;
    int lane = threadIdx.x & 31;

    float re0 = 0.f, re1 = 0.f, re2 = 0.f, re3 = 0.f;
    float im0 = 0.f, im1 = 0.f, im2 = 0.f, im3 = 0.f;

    if (lane < 24) {
        float pf  = c_primes[lane] * (PI / 89.0f);   // prime freq in [0, pi]
        float a   = __ldg(&amp[lane]);
        float ph  = __ldg(&phase[lane]);
        float cre = a * __cosf(ph);
        float cim = a * __sinf(ph);

        float d0 = (0.00f * PI - pf) * 10.0f;        // (fi - pf)/0.1
        float d1 = (0.25f * PI - pf) * 10.0f;
        float d2 = (0.50f * PI - pf) * 10.0f;
        float d3 = (0.75f * PI - pf) * 10.0f;
        float g0 = __expf(-0.5f * d0 * d0);
        float g1 = __expf(-0.5f * d1 * d1);
        float g2 = __expf(-0.5f * d2 * d2);
        float g3 = __expf(-0.5f * d3 * d3);

        re0 = cre * g0; im0 = cim * g0;
        re1 = cre * g1; im1 = cim * g1;
        re2 = cre * g2; im2 = cim * g2;
        re3 = cre * g3; im3 = cim * g3;
    }

    // Butterfly reduction: every lane ends with the full sums.
    #pragma unroll
    for (int off = 16; off > 0; off >>= 1) {
        re0 += __shfl_xor_sync(0xffffffffu, re0, off);
        im0 += __shfl_xor_sync(0xffffffffu, im0, off);
        re1 += __shfl_xor_sync(0xffffffffu, re1, off);
        im1 += __shfl_xor_sync(0xffffffffu, im1, off);
        re2 += __shfl_xor_sync(0xffffffffu, re2, off);
        im2 += __shfl_xor_sync(0xffffffffu, im2, off);
        re3 += __shfl_xor_sync(0xffffffffu, re3, off);
        im3 += __shfl_xor_sync(0xffffffffu, im3, off);
    }

    // Per-lane finish: normalization + quarter-turn IFFT (exact +-1/0 twiddles).
    float m0 = sqrtf(re0 * re0 + im0 * im0);
    float m1 = sqrtf(re1 * re1 + im1 * im1);
    float m2 = sqrtf(re2 * re2 + im2 * im2);
    float m3 = sqrtf(re3 * re3 + im3 * im3);
    float mx = fmaxf(fmaxf(m0, m1), fmaxf(m2, m3)) + 1e-8f;
    float inv = 0.25f / mx;

    // h_d = Re( (1/4) sum_k filt_k * i^{k*d} )
    const float c0 = (re0 + re1 + re2 + re3) * inv;
    const float c1 = (re0 - im1 - re2 + im3) * inv;
    const float c2 = (re0 - re1 + re2 - re3) * inv;
    const float c3 = (re0 + im1 - re2 - im3) * inv;

    // 3) Consume loads: circulant FMA + streaming stores.
    if (fast) {
        #pragma unroll
        for (int g = 0; g < GPT; g++) {
            float4 r;
            // y_n = sum_m c[(n-m) & 3] * x_m
            r.x = c0 * v[g].x + c3 * v[g].y + c2 * v[g].z + c1 * v[g].w;
            r.y = c1 * v[g].x + c0 * v[g].y + c3 * v[g].z + c2 * v[g].w;
            r.z = c2 * v[g].x + c1 * v[g].y + c0 * v[g].z + c3 * v[g].w;
            r.w = c3 * v[g].x + c2 * v[g].y + c1 * v[g].z + c0 * v[g].w;
            __stcs(&y[base + g * NTHR], r);
        }
    } else {
        #pragma unroll
        for (int g = 0; g < GPT; g++) {
            int i = base + g * NTHR;
            if (i < n_groups) {
                float4 t = __ldcs(&x[i]);
                float4 r;
                r.x = c0 * t.x + c3 * t.y + c2 * t.z + c1 * t.w;
                r.y = c1 * t.x + c0 * t.y + c3 * t.z + c2 * t.w;
                r.z = c2 * t.x + c1 * t.y + c0 * t.z + c3 * t.w;
                r.w = c3 * t.x + c2 * t.y + c1 * t.z + c0 * t.w;
                __stcs(&y[i], r);
            }
        }
    }
}

extern "C" void kernel_launch(void* const* d_in, const int* in_sizes, int n_in,
                              void* d_out, int out_size) {
    const float* qstate = (const float*)d_in[0];  // [4,2048,1024,4] f32
    const float* amp    = (const float*)d_in[1];  // [24]
    const float* phase  = (const float*)d_in[2];  // [24]
    float* out = (float*)d_out;

    int n_groups = out_size / 4;                  // 8,388,608 quaternion groups
    int per_block = NTHR * GPT;
    int blocks = (n_groups + per_block - 1) / per_block;
    fused_resonant_kernel<<<blocks, NTHR>>>(
        (const float4*)qstate, (float4*)out, amp, phase, n_groups);
}